// round 2
// baseline (speedup 1.0000x reference)
#include <cuda_runtime.h>
#include <cuda_bf16.h>

// GENConv: softmax_sg aggregation + MLP.
// h[n] = MLP( sum_e(msg_e * exp(b*msg_e)) / sum_e(exp(b*msg_e)) ) over edges with dst==n
// msg_e = relu(x[src_e]) + eps.  Softmax shift-invariance => no segment_max pass needed.
// NOTE: edge_index arrives as int32 (JAX x64 disabled downcasts int64 -> int32).

#define EPS 1e-7f
#define MAXN 100000
#define D 32

// Scratch accumulators (device globals; no allocation allowed).
__device__ float4 g_num[MAXN * 8];
__device__ float4 g_den[MAXN * 8];

__global__ void zero_accum(int n_float4_total) {
    int i = blockIdx.x * blockDim.x + threadIdx.x;
    float4 z = make_float4(0.f, 0.f, 0.f, 0.f);
    if (i < n_float4_total) {
        if (i < MAXN * 8) g_num[i] = z;
        else              g_den[i - MAXN * 8] = z;
    }
}

__global__ void edge_pass(const float4* __restrict__ x4,
                          const int* __restrict__ ei,
                          const float* __restrict__ beta_p,
                          int E) {
    int gt = blockIdx.x * blockDim.x + threadIdx.x;
    int e = gt >> 3;            // 8 lanes per edge (4 channels each)
    if (e >= E) return;
    int sub = gt & 7;

    float beta = __ldg(beta_p);
    int dst = __ldg(&ei[e]);
    int src = __ldg(&ei[E + e]);

    float4 xv = __ldg(&x4[(long long)src * 8 + sub]);

    float4 m;
    m.x = fmaxf(xv.x, 0.f) + EPS;
    m.y = fmaxf(xv.y, 0.f) + EPS;
    m.z = fmaxf(xv.z, 0.f) + EPS;
    m.w = fmaxf(xv.w, 0.f) + EPS;

    float4 ev;
    ev.x = __expf(beta * m.x);
    ev.y = __expf(beta * m.y);
    ev.z = __expf(beta * m.z);
    ev.w = __expf(beta * m.w);

    float4 nv;
    nv.x = m.x * ev.x;
    nv.y = m.y * ev.y;
    nv.z = m.z * ev.z;
    nv.w = m.w * ev.w;

    atomicAdd(&g_num[(long long)dst * 8 + sub], nv);
    atomicAdd(&g_den[(long long)dst * 8 + sub], ev);
}

// One warp per node: h = num/den, then Linear(32,64)+ReLU, Linear(64,32).
__global__ void mlp_pass(const float* __restrict__ W1, const float* __restrict__ b1,
                         const float* __restrict__ W2, const float* __restrict__ b2,
                         float* __restrict__ out, int N) {
    __shared__ float W1s[32 * 64];
    __shared__ float W2s[64 * 32];
    __shared__ float b1s[64];
    __shared__ float b2s[32];

    for (int i = threadIdx.x; i < 2048; i += blockDim.x) {
        W1s[i] = W1[i];
        W2s[i] = W2[i];
    }
    if (threadIdx.x < 64) b1s[threadIdx.x] = b1[threadIdx.x];
    if (threadIdx.x < 32) b2s[threadIdx.x] = b2[threadIdx.x];
    __syncthreads();

    const float* num = (const float*)g_num;
    const float* den = (const float*)g_den;

    int lane = threadIdx.x & 31;
    int warp = threadIdx.x >> 5;
    int warps_per_block = blockDim.x >> 5;
    int wglobal = blockIdx.x * warps_per_block + warp;
    int warps_total = gridDim.x * warps_per_block;

    for (int n = wglobal; n < N; n += warps_total) {
        float nu = num[n * 32 + lane];
        float de = den[n * 32 + lane];
        float h = (de > 0.f) ? nu / de : 0.f;

        float a0 = b1s[lane];
        float a1 = b1s[lane + 32];
#pragma unroll
        for (int i = 0; i < 32; i++) {
            float hi = __shfl_sync(0xffffffffu, h, i);
            a0 = fmaf(hi, W1s[i * 64 + lane], a0);
            a1 = fmaf(hi, W1s[i * 64 + lane + 32], a1);
        }
        a0 = fmaxf(a0, 0.f);
        a1 = fmaxf(a1, 0.f);

        float o = b2s[lane];
#pragma unroll
        for (int j = 0; j < 32; j++) {
            float t0 = __shfl_sync(0xffffffffu, a0, j);
            float t1 = __shfl_sync(0xffffffffu, a1, j);
            o = fmaf(t0, W2s[j * 32 + lane], o);
            o = fmaf(t1, W2s[(j + 32) * 32 + lane], o);
        }
        out[n * 32 + lane] = o;
    }
}

extern "C" void kernel_launch(void* const* d_in, const int* in_sizes, int n_in,
                              void* d_out, int out_size) {
    const float* x    = (const float*)d_in[0];
    const int*   ei   = (const int*)d_in[1];
    const float* beta = (const float*)d_in[2];
    const float* W1   = (const float*)d_in[3];
    const float* b1   = (const float*)d_in[4];
    const float* W2   = (const float*)d_in[5];
    const float* b2   = (const float*)d_in[6];
    float*       out  = (float*)d_out;

    int N = in_sizes[0] / D;        // 100000
    int E = in_sizes[1] / 2;        // 1600000

    // 1. zero accumulators (num + den = 2 * N * 8 float4)
    int nz = MAXN * 8 * 2;
    zero_accum<<<(nz + 255) / 256, 256>>>(nz);

    // 2. edge scatter pass: 8 threads per edge
    long long edge_threads = (long long)E * 8;
    int eb = (int)((edge_threads + 255) / 256);
    edge_pass<<<eb, 256>>>((const float4*)x, ei, beta, E);

    // 3. per-node normalize + MLP
    mlp_pass<<<1184, 256>>>(W1, b1, W2, b2, out, N);
}

// round 3
// speedup vs baseline: 1.0509x; 1.0509x over previous
#include <cuda_runtime.h>
#include <cuda_bf16.h>

// GENConv softmax_sg + MLP via CSR (counting sort by dst) — zero float atomics.
// h[n] = MLP( sum_e m*exp(b*m) / sum_e exp(b*m) ), m = relu(x[src])+eps, over dst==n.
// Softmax shift-invariance removes the segment_max pass.
// edge_index arrives as int32 (JAX x64 disabled).

#define EPS 1e-7f
#define MAXN 131072
#define MAXE 2097152

__device__ int g_deg[MAXN];
__device__ int g_off[MAXN];
__device__ int g_cur[MAXN];
__device__ int g_part[256];
__device__ int g_srcs[MAXE];

__global__ void k_zero(int N) {
    int i = blockIdx.x * blockDim.x + threadIdx.x;
    if (i < N) g_deg[i] = 0;
}

__global__ void k_hist(const int* __restrict__ ei, int E) {
    int e = blockIdx.x * blockDim.x + threadIdx.x;
    if (e < E) atomicAdd(&g_deg[ei[e]], 1);
}

// Per-block (1024) exclusive scan of deg -> off(local), block totals -> g_part.
__global__ void k_scan1(int N) {
    __shared__ int ws[32];
    int tid = threadIdx.x;
    int g = blockIdx.x * 1024 + tid;
    int v = (g < N) ? g_deg[g] : 0;
    int x = v;
#pragma unroll
    for (int o = 1; o < 32; o <<= 1) {
        int t = __shfl_up_sync(0xffffffffu, x, o);
        if ((tid & 31) >= o) x += t;
    }
    if ((tid & 31) == 31) ws[tid >> 5] = x;
    __syncthreads();
    if (tid < 32) {
        int w = ws[tid];
        int y = w;
#pragma unroll
        for (int o = 1; o < 32; o <<= 1) {
            int t = __shfl_up_sync(0xffffffffu, y, o);
            if (tid >= o) y += t;
        }
        ws[tid] = y - w;   // exclusive warp offset
    }
    __syncthreads();
    int excl = x - v + ws[tid >> 5];
    if (g < N) g_off[g] = excl;
    if (tid == 1023) g_part[blockIdx.x] = excl + v;
}

// Exclusive scan of block totals (NB <= 128), single block of 256.
__global__ void k_scan2(int NB) {
    __shared__ int ws[8];
    int tid = threadIdx.x;
    int v = (tid < NB) ? g_part[tid] : 0;
    int x = v;
#pragma unroll
    for (int o = 1; o < 32; o <<= 1) {
        int t = __shfl_up_sync(0xffffffffu, x, o);
        if ((tid & 31) >= o) x += t;
    }
    if ((tid & 31) == 31) ws[tid >> 5] = x;
    __syncthreads();
    if (tid < 8) {
        int w = ws[tid];
        int y = w;
#pragma unroll
        for (int o = 1; o < 8; o <<= 1) {
            int t = __shfl_up_sync(0xffu, y, o);
            if (tid >= o) y += t;
        }
        ws[tid] = y - w;
    }
    __syncthreads();
    int excl = x - v + ws[tid >> 5];
    if (tid < NB) g_part[tid] = excl;
}

// Add block offsets; init cursors.
__global__ void k_scan3(int N) {
    int g = blockIdx.x * blockDim.x + threadIdx.x;
    if (g < N) {
        int o = g_off[g] + g_part[g >> 10];
        g_off[g] = o;
        g_cur[g] = o;
    }
}

// Scatter src ids into CSR order.
__global__ void k_place(const int* __restrict__ ei, int E) {
    int e = blockIdx.x * blockDim.x + threadIdx.x;
    if (e < E) {
        int dst = ei[e];
        int src = ei[E + e];
        int p = atomicAdd(&g_cur[dst], 1);
        g_srcs[p] = src;
    }
}

// One warp per node: CSR gather-reduce (registers only), then MLP.
__global__ void k_agg_mlp(const float* __restrict__ xp,
                          const float* __restrict__ beta_p,
                          const float* __restrict__ W1, const float* __restrict__ b1,
                          const float* __restrict__ W2, const float* __restrict__ b2,
                          float* __restrict__ out, int N) {
    __shared__ float W1s[32 * 64];
    __shared__ float W2s[64 * 32];
    __shared__ float b1s[64];
    __shared__ float b2s[32];

    for (int i = threadIdx.x; i < 2048; i += blockDim.x) {
        W1s[i] = W1[i];
        W2s[i] = W2[i];
    }
    if (threadIdx.x < 64) b1s[threadIdx.x] = b1[threadIdx.x];
    if (threadIdx.x < 32) b2s[threadIdx.x] = b2[threadIdx.x];
    __syncthreads();

    const float beta = __ldg(beta_p);
    int lane = threadIdx.x & 31;
    int warp = threadIdx.x >> 5;
    int wpb = blockDim.x >> 5;
    int wglobal = blockIdx.x * wpb + warp;
    int warps_total = gridDim.x * wpb;

    for (int n = wglobal; n < N; n += warps_total) {
        int start = g_off[n];
        int d = g_deg[n];

        float num = 0.f, den = 0.f;
        for (int base = 0; base < d; base += 32) {
            int cnt = min(32, d - base);
            int s = 0;
            if (lane < cnt) s = g_srcs[start + base + lane];
            int j = 0;
            for (; j + 1 < cnt; j += 2) {
                int s0 = __shfl_sync(0xffffffffu, s, j);
                int s1 = __shfl_sync(0xffffffffu, s, j + 1);
                float x0 = __ldg(&xp[s0 * 32 + lane]);
                float x1 = __ldg(&xp[s1 * 32 + lane]);
                float m0 = fmaxf(x0, 0.f) + EPS;
                float m1 = fmaxf(x1, 0.f) + EPS;
                float e0 = __expf(beta * m0);
                float e1 = __expf(beta * m1);
                num = fmaf(m0, e0, num); den += e0;
                num = fmaf(m1, e1, num); den += e1;
            }
            if (j < cnt) {
                int s0 = __shfl_sync(0xffffffffu, s, j);
                float x0 = __ldg(&xp[s0 * 32 + lane]);
                float m0 = fmaxf(x0, 0.f) + EPS;
                float e0 = __expf(beta * m0);
                num = fmaf(m0, e0, num); den += e0;
            }
        }

        float h = (den > 0.f) ? num / den : 0.f;

        float a0 = b1s[lane];
        float a1 = b1s[lane + 32];
#pragma unroll
        for (int i = 0; i < 32; i++) {
            float hi = __shfl_sync(0xffffffffu, h, i);
            a0 = fmaf(hi, W1s[i * 64 + lane], a0);
            a1 = fmaf(hi, W1s[i * 64 + lane + 32], a1);
        }
        a0 = fmaxf(a0, 0.f);
        a1 = fmaxf(a1, 0.f);

        float o = b2s[lane];
#pragma unroll
        for (int jj = 0; jj < 32; jj++) {
            float t0 = __shfl_sync(0xffffffffu, a0, jj);
            float t1 = __shfl_sync(0xffffffffu, a1, jj);
            o = fmaf(t0, W2s[jj * 32 + lane], o);
            o = fmaf(t1, W2s[(jj + 32) * 32 + lane], o);
        }
        out[n * 32 + lane] = o;
    }
}

extern "C" void kernel_launch(void* const* d_in, const int* in_sizes, int n_in,
                              void* d_out, int out_size) {
    const float* x    = (const float*)d_in[0];
    const int*   ei   = (const int*)d_in[1];
    const float* beta = (const float*)d_in[2];
    const float* W1   = (const float*)d_in[3];
    const float* b1   = (const float*)d_in[4];
    const float* W2   = (const float*)d_in[5];
    const float* b2   = (const float*)d_in[6];
    float*       out  = (float*)d_out;

    int N = in_sizes[0] / 32;   // 100000
    int E = in_sizes[1] / 2;    // 1600000
    int NB = (N + 1023) / 1024; // scan blocks (98)

    k_zero<<<(N + 255) / 256, 256>>>(N);
    k_hist<<<(E + 255) / 256, 256>>>(ei, E);
    k_scan1<<<NB, 1024>>>(N);
    k_scan2<<<1, 256>>>(NB);
    k_scan3<<<(N + 255) / 256, 256>>>(N);
    k_place<<<(E + 255) / 256, 256>>>(ei, E);
    k_agg_mlp<<<1184, 256>>>(x, beta, W1, b1, W2, b2, out, N);
}